// round 4
// baseline (speedup 1.0000x reference)
#include <cuda_runtime.h>
#include <cstdint>

#define B_  64
#define P_  2048
#define D_  1024
#define TILE_M 128
#define KC 16
#define NSTAGE (D_ / KC)       /* 64 stages */
#define PITCH 112              /* bytes/row: 64 data + 48 pad; 7r+u quad bijection */
#define A_OFF 0
#define B_OFF (TILE_M * PITCH)            /* 14336 */
#define STAGE (B_OFF + B_ * PITCH)        /* 21504 */
#define MT16 (16 * PITCH)                 /* 1792 */

/* simMax as order-preserving uint keys; 0 == -inf sentinel; loss_kernel resets. */
__device__ unsigned int g_key[B_ * B_];

__device__ __forceinline__ uint32_t smem_u32(const void* p) {
    uint32_t a;
    asm("{ .reg .u64 t; cvta.to.shared.u64 t, %1; cvt.u32.u64 %0, t; }" : "=r"(a) : "l"(p));
    return a;
}
__device__ __forceinline__ uint32_t pack_bf16x2(float lo_e, float hi_e) {
    uint32_t h;
    asm("cvt.rn.bf16x2.f32 %0, %1, %2;" : "=r"(h) : "f"(hi_e), "f"(lo_e));
    return h;
}
/* 8 consecutive fp32 -> hi 16B @addr, lo 16B @addr+32 */
__device__ __forceinline__ void cvt_sts8(uint32_t addr, float4 v0, float4 v1) {
    uint32_t h0 = pack_bf16x2(v0.x, v0.y);
    uint32_t h1 = pack_bf16x2(v0.z, v0.w);
    uint32_t h2 = pack_bf16x2(v1.x, v1.y);
    uint32_t h3 = pack_bf16x2(v1.z, v1.w);
    uint32_t l0 = pack_bf16x2(v0.x - __uint_as_float(h0 << 16), v0.y - __uint_as_float(h0 & 0xFFFF0000u));
    uint32_t l1 = pack_bf16x2(v0.z - __uint_as_float(h1 << 16), v0.w - __uint_as_float(h1 & 0xFFFF0000u));
    uint32_t l2 = pack_bf16x2(v1.x - __uint_as_float(h2 << 16), v1.y - __uint_as_float(h2 & 0xFFFF0000u));
    uint32_t l3 = pack_bf16x2(v1.z - __uint_as_float(h3 << 16), v1.w - __uint_as_float(h3 & 0xFFFF0000u));
    asm volatile("st.shared.v4.b32 [%0], {%1,%2,%3,%4};" :: "r"(addr), "r"(h0), "r"(h1), "r"(h2), "r"(h3) : "memory");
    asm volatile("st.shared.v4.b32 [%0], {%1,%2,%3,%4};" :: "r"(addr + 32), "r"(l0), "r"(l1), "r"(l2), "r"(l3) : "memory");
}
__device__ __forceinline__ void ldsm4(uint32_t* r, uint32_t addr) {
    asm volatile("ldmatrix.sync.aligned.m8n8.x4.shared.b16 {%0,%1,%2,%3}, [%4];"
                 : "=r"(r[0]), "=r"(r[1]), "=r"(r[2]), "=r"(r[3]) : "r"(addr));
}
__device__ __forceinline__ void mma16816(float* c, const uint32_t* a, const uint32_t* b) {
    asm volatile(
        "mma.sync.aligned.m16n8k16.row.col.f32.bf16.bf16.f32 "
        "{%0,%1,%2,%3}, {%4,%5,%6,%7}, {%8,%9}, {%0,%1,%2,%3};"
        : "+f"(c[0]), "+f"(c[1]), "+f"(c[2]), "+f"(c[3])
        : "r"(a[0]), "r"(a[1]), "r"(a[2]), "r"(a[3]), "r"(b[0]), "r"(b[1]));
}

/* Grid (16,64), 256 thr. CTA: sim[128p x 64c] split-bf16 HMMA, per-col max -> g_key */
__global__ __launch_bounds__(256, 2)
void gemm_max_kernel(const float* __restrict__ im, const float* __restrict__ dis) {
    __shared__ __align__(128) char smem[2 * STAGE];   /* 43008 B */
    const uint32_t sb = smem_u32(smem);
    const int tid = threadIdx.x, lid = tid & 31, wid = tid >> 5;
    const int wm = wid & 3, wn = wid >> 2;
    const int b = blockIdx.y, pt = blockIdx.x;

    /* gmem + STS mapping: A row r = tid&127, half h = tid>>7 (8 floats) */
    const int ar = tid & 127, ah = tid >> 7;
    const float* aP = im + ((size_t)(b * P_ + pt * TILE_M + ar)) * D_ + ah * 8;
    const uint32_t aSt = A_OFF + (uint32_t)(ar * PITCH + ah * 16);
    /* B: threads 0-127 only: row c = tid&63, half hB = (tid>>6)&1 */
    const int bc = tid & 63, bh = (tid >> 6) & 1;
    const bool doB = tid < 128;
    const float* bP = dis + (size_t)bc * D_ + bh * 8;
    const uint32_t bSt = B_OFF + (uint32_t)(bc * PITCH + bh * 16);

    /* ldmatrix lane addresses */
    const uint32_t aLd = A_OFF + (uint32_t)((wm * 32 + (lid & 15)) * PITCH + (lid >> 4) * 16);
    const uint32_t bLd = B_OFF + (uint32_t)((wn * 32 + (lid >> 4) * 8 + (lid & 7)) * PITCH
                                            + ((lid >> 3) & 1) * 16);

    float acc[2][4][4];
    #pragma unroll
    for (int i = 0; i < 2; ++i)
        #pragma unroll
        for (int j = 0; j < 4; ++j)
            #pragma unroll
            for (int k = 0; k < 4; ++k) acc[i][j][k] = 0.f;

    float4 va[2][2], vb[2][2];
    va[0][0] = *(const float4*)(aP);      va[0][1] = *(const float4*)(aP + 4);
    va[1][0] = *(const float4*)(aP + 16); va[1][1] = *(const float4*)(aP + 20);
    if (doB) {
        vb[0][0] = *(const float4*)(bP);      vb[0][1] = *(const float4*)(bP + 4);
        vb[1][0] = *(const float4*)(bP + 16); vb[1][1] = *(const float4*)(bP + 20);
    }
    cvt_sts8(sb + aSt, va[0][0], va[0][1]);
    if (doB) cvt_sts8(sb + bSt, vb[0][0], vb[0][1]);
    __syncthreads();

    #pragma unroll 2
    for (int kt = 0; kt < NSTAGE; ++kt) {
        const uint32_t cur = sb + (uint32_t)((kt & 1) * STAGE);
        const uint32_t nxt = sb + (uint32_t)(((kt + 1) & 1) * STAGE);

        uint32_t Ah[2][4], Al[2][4], Bh[2][4], Bl[2][4];
        ldsm4(Ah[0], cur + aLd);               ldsm4(Al[0], cur + aLd + 32);
        ldsm4(Ah[1], cur + aLd + MT16);        ldsm4(Al[1], cur + aLd + MT16 + 32);
        ldsm4(Bh[0], cur + bLd);               ldsm4(Bl[0], cur + bLd + 32);
        ldsm4(Bh[1], cur + bLd + MT16);        ldsm4(Bl[1], cur + bLd + MT16 + 32);

        if (kt + 2 < NSTAGE) {   /* prefetch stage kt+2 into slot kt&1 */
            const int s = kt & 1;
            const float* a2 = aP + (kt + 2) * KC;
            va[s][0] = *(const float4*)(a2);
            va[s][1] = *(const float4*)(a2 + 4);
            if (doB) {
                const float* b2 = bP + (kt + 2) * KC;
                vb[s][0] = *(const float4*)(b2);
                vb[s][1] = *(const float4*)(b2 + 4);
            }
        }
        if (kt + 1 < NSTAGE) {   /* convert + store stage kt+1 */
            const int s = (kt + 1) & 1;
            cvt_sts8(nxt + aSt, va[s][0], va[s][1]);
            if (doB) cvt_sts8(nxt + bSt, vb[s][0], vb[s][1]);
        }

        #pragma unroll
        for (int mt = 0; mt < 2; ++mt)
            #pragma unroll
            for (int nt = 0; nt < 4; ++nt) {
                const uint32_t* bhp = &Bh[nt >> 1][(nt & 1) * 2];
                const uint32_t* blp = &Bl[nt >> 1][(nt & 1) * 2];
                mma16816(acc[mt][nt], Ah[mt], bhp);   /* hi*hi */
                mma16816(acc[mt][nt], Ah[mt], blp);   /* hi*lo */
                mma16816(acc[mt][nt], Al[mt], bhp);   /* lo*hi */
            }
        __syncthreads();
    }

    /* epilogue: fragments -> smem -> per-column max -> atomicMax */
    float* red = (float*)smem;   /* [128][66] = 33792 B, fits */
    const int g = lid >> 2, t = lid & 3;
    #pragma unroll
    for (int mt = 0; mt < 2; ++mt) {
        const int r0 = wm * 32 + mt * 16 + g;
        #pragma unroll
        for (int nt = 0; nt < 4; ++nt) {
            const int c = wn * 32 + nt * 8 + t * 2;
            red[r0 * 66 + c]           = acc[mt][nt][0];
            red[r0 * 66 + c + 1]       = acc[mt][nt][1];
            red[(r0 + 8) * 66 + c]     = acc[mt][nt][2];
            red[(r0 + 8) * 66 + c + 1] = acc[mt][nt][3];
        }
    }
    __syncthreads();
    if (tid < 64) {
        float m = -3.4e38f;
        #pragma unroll 8
        for (int r = 0; r < TILE_M; ++r) m = fmaxf(m, red[r * 66 + tid]);
        unsigned int k = __float_as_uint(m);
        k = (k & 0x80000000u) ? ~k : (k | 0x80000000u);
        atomicMax(&g_key[b * B_ + tid], k);
    }
}

/* decode simMax, bidirectional hinge loss, reset g_key for next replay */
__global__ void loss_kernel(const void* __restrict__ lblRaw, float* __restrict__ out) {
    __shared__ float sm[B_][B_ + 1];
    __shared__ int lab[B_];
    __shared__ int s_is64;
    __shared__ float rr[3][8];
    const int tid = threadIdx.x;

    for (int e = tid; e < B_ * B_; e += 256) {
        const unsigned int u = g_key[e];
        sm[e >> 6][e & 63] = __uint_as_float((u & 0x80000000u) ? (u ^ 0x80000000u) : ~u);
    }
    /* labels in [0,64): int64 buffer has all-zero odd int32 words */
    if (tid < 32) {
        int odd = ((const int*)lblRaw)[2 * tid + 1];
        unsigned m = __ballot_sync(0xFFFFFFFFu, odd != 0);
        if (tid == 0) s_is64 = (m == 0u);
    }
    __syncthreads();
    if (tid < B_)
        lab[tid] = s_is64 ? (int)((const long long*)lblRaw)[tid] : ((const int*)lblRaw)[tid];
    __syncthreads();
    for (int e = tid; e < B_ * B_; e += 256) g_key[e] = 0u;   /* reset for replays */

    float s1 = 0.f, s2 = 0.f, n = 0.f;
    for (int e = tid; e < B_ * B_; e += 256) {
        const int i = e >> 6, j = e & 63;
        if (lab[i] != lab[j]) {
            n += 1.f;
            const float p = sm[i][i];
            s1 += fmaxf(sm[i][j] - p + 0.1f, 0.f);
            s2 += fmaxf(sm[j][i] - p + 0.1f, 0.f);
        }
    }
    #pragma unroll
    for (int o = 16; o > 0; o >>= 1) {
        s1 += __shfl_down_sync(0xFFFFFFFFu, s1, o);
        s2 += __shfl_down_sync(0xFFFFFFFFu, s2, o);
        n  += __shfl_down_sync(0xFFFFFFFFu, n,  o);
    }
    if ((tid & 31) == 0) { rr[0][tid >> 5] = s1; rr[1][tid >> 5] = s2; rr[2][tid >> 5] = n; }
    __syncthreads();
    if (tid == 0) {
        float a = 0.f, c = 0.f, d = 0.f;
        #pragma unroll
        for (int w = 0; w < 8; ++w) { a += rr[0][w]; c += rr[1][w]; d += rr[2][w]; }
        out[0] = (a + c) / (d + 1e-6f);
    }
}

extern "C" void kernel_launch(void* const* d_in, const int* in_sizes, int n_in,
                              void* d_out, int out_size) {
    (void)in_sizes; (void)n_in; (void)out_size;
    const float* im  = (const float*)d_in[0];
    const float* dis = (const float*)d_in[1];
    const void*  lbl = d_in[2];

    dim3 grid(P_ / TILE_M, B_);
    gemm_max_kernel<<<grid, 256>>>(im, dis);
    loss_kernel<<<1, 256>>>(lbl, (float*)d_out);
}